// round 1
// baseline (speedup 1.0000x reference)
#include <cuda_runtime.h>
#include <math.h>

#define NW 14
#define NL 4
#define NSTATE (1 << NW)
#define THREADS 512
#define PI_F 3.14159265358979323846f

// ---------- complex helpers ----------
__device__ __forceinline__ float2 cmul(float2 a, float2 b) {
    return make_float2(a.x * b.x - a.y * b.y, a.x * b.y + a.y * b.x);
}
__device__ __forceinline__ float2 cadd(float2 a, float2 b) {
    return make_float2(a.x + b.x, a.y + b.y);
}

// XOR swizzle over the low 5 bits of the float2 index: makes every pass's
// per-warp access pattern a lane permutation -> conflict-free LDS/STS.
__device__ __forceinline__ int sw(int i) { return i ^ ((i >> 5) & 31); }

// Apply one 2x2 complex gate to local register block r[32] on local bit L.
template <int L>
__device__ __forceinline__ void apply_gate(float2* r, const float2* __restrict__ g) {
    const float2 u00 = g[0], u01 = g[1], u10 = g[2], u11 = g[3];
#pragma unroll
    for (int p = 0; p < 16; p++) {
        const int lowmask = (1 << L) - 1;
        const int j0 = ((p & ~lowmask) << 1) | (p & lowmask);
        const int j1 = j0 | (1 << L);
        float2 x0 = r[j0], x1 = r[j1];
        float2 y0, y1;
        y0.x = fmaf(u00.x, x0.x, fmaf(-u00.y, x0.y, fmaf(u01.x, x1.x, -u01.y * x1.y)));
        y0.y = fmaf(u00.x, x0.y, fmaf( u00.y, x0.x, fmaf(u01.x, x1.y,  u01.y * x1.x)));
        y1.x = fmaf(u10.x, x0.x, fmaf(-u10.y, x0.y, fmaf(u11.x, x1.x, -u11.y * x1.y)));
        y1.y = fmaf(u10.x, x0.y, fmaf( u10.y, x0.x, fmaf(u11.x, x1.y,  u11.y * x1.x)));
        r[j0] = y0;
        r[j1] = y1;
    }
}

// CNOT chain CNOT(0,1),CNOT(1,2),...,CNOT(12,13),CNOT(13,0) as a basis
// permutation. Index bit k = wire (13-k). dst_k = XOR of src bits k..13 for
// k<=12; dst_13 = XOR of src bits 0..12.
__device__ __forceinline__ unsigned cnot_perm(unsigned i) {
    unsigned s = i;
    s ^= s >> 1; s ^= s >> 2; s ^= s >> 4; s ^= s >> 8;   // s_k = xor of bits k..13
    return (s & 0x1FFFu) | (((s ^ (i >> 13)) & 1u) << 13);
}

__global__ __launch_bounds__(THREADS, 1)
void vqc_kernel(const float* __restrict__ x_raw,
                const float* __restrict__ angles,
                float* __restrict__ out) {
    extern __shared__ unsigned char smem[];
    float2* sv   = (float2*)smem;              // [NSTATE] statevector
    float2* sU   = sv + NSTATE;                // [NL*NW*4] fused gates
    float2* senc = sU + NL * NW * 4;           // [NW] (cos, sin) encoding factors
    float*  sred = (float*)(senc + NW);        // [16] reduction scratch

    const int tid = threadIdx.x;
    const int b   = blockIdx.x;

    // ---- build encoding factors (c,s) per wire ----
    if (tid < NW) {
        float t = tanhf(x_raw[b * NW + tid]) * PI_F;
        senc[tid] = make_float2(cosf(0.5f * t), sinf(0.5f * t));
    }
    // ---- build fused U = RZ(a2) * RY(a1) * RX(a0) per (layer, wire) ----
    if (tid < NL * NW) {
        const int k = tid / NW, w = tid % NW;
        const float a0 = angles[(k * NW + w) * 3 + 0];
        const float a1 = angles[(k * NW + w) * 3 + 1];
        const float a2 = angles[(k * NW + w) * 3 + 2];
        const float c0 = cosf(0.5f * a0), s0 = sinf(0.5f * a0);
        const float c1 = cosf(0.5f * a1), s1 = sinf(0.5f * a1);
        const float2 rx00 = make_float2(c0, 0.f), rx01 = make_float2(0.f, -s0);
        const float2 rx10 = make_float2(0.f, -s0), rx11 = make_float2(c0, 0.f);
        const float2 ry00 = make_float2(c1, 0.f), ry01 = make_float2(-s1, 0.f);
        const float2 ry10 = make_float2(s1, 0.f), ry11 = make_float2(c1, 0.f);
        // M = RY * RX
        float2 m00 = cadd(cmul(ry00, rx00), cmul(ry01, rx10));
        float2 m01 = cadd(cmul(ry00, rx01), cmul(ry01, rx11));
        float2 m10 = cadd(cmul(ry10, rx00), cmul(ry11, rx10));
        float2 m11 = cadd(cmul(ry10, rx01), cmul(ry11, rx11));
        // U = RZ * M  (row0 *= e^{-i a2/2}, row1 *= e^{+i a2/2})
        const float2 em = make_float2(cosf(0.5f * a2), -sinf(0.5f * a2));
        const float2 ep = make_float2(em.x, -em.y);
        float2* g = sU + tid * 4;
        g[0] = cmul(em, m00); g[1] = cmul(em, m01);
        g[2] = cmul(ep, m10); g[3] = cmul(ep, m11);
    }
    __syncthreads();

    float2 r[32];

    for (int k = 0; k < NL; k++) {
        const float2* Gk = sU + k * NW * 4;

        // ================= Pass A: i = tid*32 + j, wires 9..13 (j bits 4..0)
        if (k == 0) {
            // Build product state directly in registers (RY encoding of |0..0>).
            // i bits 13..5 = tid bits 8..0 -> wire w (w<=8) is tid bit (8-w).
            float common = 1.f;
#pragma unroll
            for (int w = 0; w < 9; w++) {
                float2 cs = senc[w];
                common *= ((tid >> (8 - w)) & 1) ? cs.y : cs.x;
            }
            r[0].x = common;
#pragma unroll
            for (int st = 0; st < 5; st++) {   // wires 9..13 expand MSB->LSB of j
                float2 cs = senc[9 + st];
#pragma unroll
                for (int kk = (1 << st) - 1; kk >= 0; kk--) {
                    float v = r[kk].x;
                    r[2 * kk + 1].x = v * cs.y;
                    r[2 * kk].x     = v * cs.x;
                }
            }
#pragma unroll
            for (int j = 0; j < 32; j++) r[j].y = 0.f;
        } else {
            const int m = tid & 31, base = tid * 32;
#pragma unroll
            for (int j = 0; j < 32; j++) r[j] = sv[base + (j ^ m)];
        }
        apply_gate<4>(r, Gk + 9 * 4);
        apply_gate<3>(r, Gk + 10 * 4);
        apply_gate<2>(r, Gk + 11 * 4);
        apply_gate<1>(r, Gk + 12 * 4);
        apply_gate<0>(r, Gk + 13 * 4);
        {
            const int m = tid & 31, base = tid * 32;
#pragma unroll
            for (int j = 0; j < 32; j++) sv[base + (j ^ m)] = r[j];
        }
        __syncthreads();

        // ================= Pass B: i = ((tid>>5)<<10) | (j<<5) | (tid&31), wires 4..8
        {
            const int hi = (tid >> 5) << 10, lo = tid & 31;
#pragma unroll
            for (int j = 0; j < 32; j++) r[j] = sv[hi + (j << 5) + (lo ^ j)];
        }
        apply_gate<4>(r, Gk + 4 * 4);
        apply_gate<3>(r, Gk + 5 * 4);
        apply_gate<2>(r, Gk + 6 * 4);
        apply_gate<1>(r, Gk + 7 * 4);
        apply_gate<0>(r, Gk + 8 * 4);
        {
            const int hi = (tid >> 5) << 10, lo = tid & 31;
#pragma unroll
            for (int j = 0; j < 32; j++) sv[hi + (j << 5) + (lo ^ j)] = r[j];
        }
        __syncthreads();

        // ================= Pass C: i = (j<<9) | tid, wires 0..3 (j bits 4..1)
        {
            const int mid = (tid >> 5) & 15;
#pragma unroll
            for (int j = 0; j < 32; j++) {
                int sl = (j << 9) | (tid ^ mid ^ ((j & 1) << 4));
                r[j] = sv[sl];
            }
        }
        apply_gate<4>(r, Gk + 0 * 4);
        apply_gate<3>(r, Gk + 1 * 4);
        apply_gate<2>(r, Gk + 2 * 4);
        apply_gate<1>(r, Gk + 3 * 4);

        if (k < NL - 1) {
            // Fuse the CNOT-chain permutation into the store.
#pragma unroll
            for (int j = 0; j < 32; j++) {
                unsigned i = (unsigned)((j << 9) | tid);
                unsigned d = cnot_perm(i);
                sv[sw((int)d)] = r[j];
            }
            __syncthreads();
        } else {
            // Last layer: measurement sign = permuted bit13 = parity(src bits 0..12).
            float acc = 0.f;
#pragma unroll
            for (int j = 0; j < 32; j++) {
                int i = (j << 9) | tid;
                float v = fmaf(r[j].x, r[j].x, r[j].y * r[j].y);
                acc += (__popc(i & 0x1FFF) & 1) ? -v : v;
            }
#pragma unroll
            for (int off = 16; off; off >>= 1)
                acc += __shfl_xor_sync(0xffffffffu, acc, off);
            if ((tid & 31) == 0) sred[tid >> 5] = acc;
            __syncthreads();
            if (tid < 32) {
                float v = (tid < 16) ? sred[tid] : 0.f;
#pragma unroll
                for (int off = 8; off; off >>= 1)
                    v += __shfl_xor_sync(0xffffffffu, v, off);
                if (tid == 0) out[b] = v;
            }
        }
    }
}

extern "C" void kernel_launch(void* const* d_in, const int* in_sizes, int n_in,
                              void* d_out, int out_size) {
    const float* x   = (const float*)d_in[0];
    const float* ang = (const float*)d_in[1];
    if (n_in >= 2 && in_sizes[0] == NL * NW * 3 && in_sizes[1] != NL * NW * 3) {
        // defensive: inputs swapped
        const float* t = x; x = ang; ang = t;
    }
    float* out = (float*)d_out;

    const int smem_bytes = (NSTATE + NL * NW * 4 + NW) * (int)sizeof(float2)
                         + 16 * (int)sizeof(float);
    cudaFuncSetAttribute(vqc_kernel, cudaFuncAttributeMaxDynamicSharedMemorySize,
                         smem_bytes);
    vqc_kernel<<<1024, THREADS, smem_bytes>>>(x, ang, out);
}

// round 2
// speedup vs baseline: 1.0302x; 1.0302x over previous
#include <cuda_runtime.h>
#include <math.h>

#define NW 14
#define NL 4
#define NSTATE (1 << NW)
#define THREADS 512
#define PI_F 3.14159265358979323846f

typedef unsigned long long u64;

// ---------- packed f32x2 helpers (sm_103a FFMA2 path) ----------
__device__ __forceinline__ u64 pk(float lo, float hi) {
    u64 r; asm("mov.b64 %0, {%1, %2};" : "=l"(r) : "f"(lo), "f"(hi)); return r;
}
__device__ __forceinline__ void unpk(u64 a, float& lo, float& hi) {
    asm("mov.b64 {%0, %1}, %2;" : "=f"(lo), "=f"(hi) : "l"(a));
}
__device__ __forceinline__ u64 swp(u64 a) {
    float lo, hi; unpk(a, lo, hi);
    u64 r; asm("mov.b64 %0, {%1, %2};" : "=l"(r) : "f"(hi), "f"(lo)); return r;
}
__device__ __forceinline__ u64 ffma2_(u64 a, u64 b, u64 c) {
    u64 d; asm("fma.rn.f32x2 %0, %1, %2, %3;" : "=l"(d) : "l"(a), "l"(b), "l"(c));
    return d;
}
__device__ __forceinline__ u64 fmul2_(u64 a, u64 b) {
    u64 d; asm("mul.rn.f32x2 %0, %1, %2;" : "=l"(d) : "l"(a), "l"(b));
    return d;
}

// float2 complex helpers for gate fusion (host-side of the CTA, tiny)
__device__ __forceinline__ float2 cmul(float2 a, float2 b) {
    return make_float2(a.x * b.x - a.y * b.y, a.x * b.y + a.y * b.x);
}
__device__ __forceinline__ float2 cadd(float2 a, float2 b) {
    return make_float2(a.x + b.x, a.y + b.y);
}

// XOR swizzle over low 5 bits of the u64 index -> conflict-free LDS/STS.
__device__ __forceinline__ int sw(int i) { return i ^ ((i >> 5) & 31); }

// Packed complex 2x2 gate on local bit L of register block r[32].
// Gate g: 8 packed constants {B00,P00,B01,P01,B10,P10,B11,P11},
//   B = (u.re, u.re), P = (-u.im, +u.im).
// y = B*X + P*swap(X) implements complex multiply in 2 packed ops.
template <int L>
__device__ __forceinline__ void apply_gate(u64* r, const u64* __restrict__ g) {
    const u64 B00 = g[0], P00 = g[1], B01 = g[2], P01 = g[3];
    const u64 B10 = g[4], P10 = g[5], B11 = g[6], P11 = g[7];
#pragma unroll
    for (int p = 0; p < 16; p++) {
        const int lm = (1 << L) - 1;
        const int j0 = ((p & ~lm) << 1) | (p & lm);
        const int j1 = j0 | (1 << L);
        u64 x0 = r[j0], x1 = r[j1];
        u64 x0s = swp(x0), x1s = swp(x1);
        r[j0] = ffma2_(B00, x0, ffma2_(P00, x0s, ffma2_(B01, x1, fmul2_(P01, x1s))));
        r[j1] = ffma2_(B10, x0, ffma2_(P10, x0s, ffma2_(B11, x1, fmul2_(P11, x1s))));
    }
}

// CNOT chain CNOT(0,1)..CNOT(12,13),CNOT(13,0) as basis permutation.
// Index bit k = wire (13-k). dst_k = xor(src bits k..13) for k<=12;
// dst_13 = xor(src bits 0..12).
__device__ __forceinline__ unsigned cnot_perm(unsigned i) {
    unsigned s = i;
    s ^= s >> 1; s ^= s >> 2; s ^= s >> 4; s ^= s >> 8;
    return (s & 0x1FFFu) | (((s ^ (i >> 13)) & 1u) << 13);
}

__global__ __launch_bounds__(THREADS, 1)
void vqc_kernel(const float* __restrict__ x_raw,
                const float* __restrict__ angles,
                float* __restrict__ out) {
    extern __shared__ unsigned char smem[];
    u64*    sv   = (u64*)smem;                 // [NSTATE] statevector (re,im packed)
    u64*    sU   = sv + NSTATE;                // [NL*NW*8] packed gate constants
    float2* senc = (float2*)(sU + NL * NW * 8);// [NW] (cos,sin) encoding factors
    float*  sred = (float*)(senc + NW);        // [16] reduction scratch

    const int tid = threadIdx.x;
    const int b   = blockIdx.x;

    // ---- encoding factors ----
    if (tid < NW) {
        float t = tanhf(x_raw[b * NW + tid]) * PI_F;
        senc[tid] = make_float2(cosf(0.5f * t), sinf(0.5f * t));
    }
    // ---- fused U = RZ*RY*RX per (layer,wire), stored as packed constants ----
    if (tid < NL * NW) {
        const int k = tid / NW, w = tid % NW;
        const float a0 = angles[(k * NW + w) * 3 + 0];
        const float a1 = angles[(k * NW + w) * 3 + 1];
        const float a2 = angles[(k * NW + w) * 3 + 2];
        const float c0 = cosf(0.5f * a0), s0 = sinf(0.5f * a0);
        const float c1 = cosf(0.5f * a1), s1 = sinf(0.5f * a1);
        const float2 rx00 = make_float2(c0, 0.f),  rx01 = make_float2(0.f, -s0);
        const float2 rx10 = make_float2(0.f, -s0), rx11 = make_float2(c0, 0.f);
        const float2 ry00 = make_float2(c1, 0.f),  ry01 = make_float2(-s1, 0.f);
        const float2 ry10 = make_float2(s1, 0.f),  ry11 = make_float2(c1, 0.f);
        float2 m00 = cadd(cmul(ry00, rx00), cmul(ry01, rx10));
        float2 m01 = cadd(cmul(ry00, rx01), cmul(ry01, rx11));
        float2 m10 = cadd(cmul(ry10, rx00), cmul(ry11, rx10));
        float2 m11 = cadd(cmul(ry10, rx01), cmul(ry11, rx11));
        const float2 em = make_float2(cosf(0.5f * a2), -sinf(0.5f * a2));
        const float2 ep = make_float2(em.x, -em.y);
        float2 u00 = cmul(em, m00), u01 = cmul(em, m01);
        float2 u10 = cmul(ep, m10), u11 = cmul(ep, m11);
        u64* g = sU + tid * 8;
        g[0] = pk(u00.x, u00.x); g[1] = pk(-u00.y, u00.y);
        g[2] = pk(u01.x, u01.x); g[3] = pk(-u01.y, u01.y);
        g[4] = pk(u10.x, u10.x); g[5] = pk(-u10.y, u10.y);
        g[6] = pk(u11.x, u11.x); g[7] = pk(-u11.y, u11.y);
    }
    __syncthreads();

    u64 r[32];

    for (int k = 0; k < NL; k++) {
        const u64* Gk = sU + k * NW * 8;

        // ===== Pass A: i = tid*32 + j, wires 9..13 (j bits 4..0) =====
        if (k == 0) {
            // RY-encoded product state built directly in registers.
            float v[32];
            float common = 1.f;
#pragma unroll
            for (int w = 0; w < 9; w++) {
                float2 cs = senc[w];
                common *= ((tid >> (8 - w)) & 1) ? cs.y : cs.x;
            }
            v[0] = common;
#pragma unroll
            for (int st = 0; st < 5; st++) {
                float2 cs = senc[9 + st];
#pragma unroll
                for (int kk = (1 << st) - 1; kk >= 0; kk--) {
                    float t = v[kk];
                    v[2 * kk + 1] = t * cs.y;
                    v[2 * kk]     = t * cs.x;
                }
            }
#pragma unroll
            for (int j = 0; j < 32; j++) r[j] = pk(v[j], 0.f);
        } else {
            const int m = tid & 31, base = tid * 32;
#pragma unroll
            for (int j = 0; j < 32; j++) r[j] = sv[base + (j ^ m)];
        }
        apply_gate<4>(r, Gk + 9 * 8);
        apply_gate<3>(r, Gk + 10 * 8);
        apply_gate<2>(r, Gk + 11 * 8);
        apply_gate<1>(r, Gk + 12 * 8);
        apply_gate<0>(r, Gk + 13 * 8);
        {
            const int m = tid & 31, base = tid * 32;
#pragma unroll
            for (int j = 0; j < 32; j++) sv[base + (j ^ m)] = r[j];
        }
        __syncthreads();

        // ===== Pass B: i = ((tid>>5)<<10)|(j<<5)|(tid&31), wires 4..8 =====
        {
            const int hi = (tid >> 5) << 10, lo = tid & 31;
#pragma unroll
            for (int j = 0; j < 32; j++) r[j] = sv[hi + (j << 5) + (lo ^ j)];
        }
        apply_gate<4>(r, Gk + 4 * 8);
        apply_gate<3>(r, Gk + 5 * 8);
        apply_gate<2>(r, Gk + 6 * 8);
        apply_gate<1>(r, Gk + 7 * 8);
        apply_gate<0>(r, Gk + 8 * 8);
        {
            const int hi = (tid >> 5) << 10, lo = tid & 31;
#pragma unroll
            for (int j = 0; j < 32; j++) sv[hi + (j << 5) + (lo ^ j)] = r[j];
        }
        __syncthreads();

        // ===== Pass C: i = (j<<9) | tid, wires 0..3 (j bits 4..1) =====
        {
            const int mid = (tid >> 5) & 15;
#pragma unroll
            for (int j = 0; j < 32; j++) {
                int sl = (j << 9) | (tid ^ mid ^ ((j & 1) << 4));
                r[j] = sv[sl];
            }
        }
        apply_gate<4>(r, Gk + 0 * 8);
        apply_gate<3>(r, Gk + 1 * 8);
        apply_gate<2>(r, Gk + 2 * 8);
        apply_gate<1>(r, Gk + 3 * 8);

        if (k < NL - 1) {
            // Fuse the CNOT-chain permutation into the store.
#pragma unroll
            for (int j = 0; j < 32; j++) {
                unsigned i = (unsigned)((j << 9) | tid);
                unsigned d = cnot_perm(i);
                sv[sw((int)d)] = r[j];
            }
            __syncthreads();
        } else {
            // <Z0>: sign = permuted bit13 = parity(src bits 0..12).
            float acc = 0.f;
#pragma unroll
            for (int j = 0; j < 32; j++) {
                int i = (j << 9) | tid;
                float re, im; unpk(r[j], re, im);
                float vv = fmaf(re, re, im * im);
                acc += (__popc(i & 0x1FFF) & 1) ? -vv : vv;
            }
#pragma unroll
            for (int off = 16; off; off >>= 1)
                acc += __shfl_xor_sync(0xffffffffu, acc, off);
            if ((tid & 31) == 0) sred[tid >> 5] = acc;
            __syncthreads();
            if (tid < 32) {
                float v = (tid < 16) ? sred[tid] : 0.f;
#pragma unroll
                for (int off = 8; off; off >>= 1)
                    v += __shfl_xor_sync(0xffffffffu, v, off);
                if (tid == 0) out[b] = v;
            }
        }
    }
}

extern "C" void kernel_launch(void* const* d_in, const int* in_sizes, int n_in,
                              void* d_out, int out_size) {
    const float* x   = (const float*)d_in[0];
    const float* ang = (const float*)d_in[1];
    if (n_in >= 2 && in_sizes[0] == NL * NW * 3 && in_sizes[1] != NL * NW * 3) {
        const float* t = x; x = ang; ang = t;
    }
    float* out = (float*)d_out;

    const int smem_bytes = NSTATE * 8 + NL * NW * 8 * 8 + NW * 8 + 16 * 4;
    cudaFuncSetAttribute(vqc_kernel, cudaFuncAttributeMaxDynamicSharedMemorySize,
                         smem_bytes);
    vqc_kernel<<<1024, THREADS, smem_bytes>>>(x, ang, out);
}